// round 2
// baseline (speedup 1.0000x reference)
#include <cuda_runtime.h>
#include <cuda_bf16.h>
#include <stdint.h>

// Problem constants (fixed by the reference)
#define B_   64
#define N_   2048
#define D_   512
#define K_   64
#define KG_  80                      // K + ghost clusters
#define ROWS_TOTAL (B_ * N_)         // 131072

// ---------------- scratch (__device__ globals: allocation-free) -------------
__device__ float          g_a[(size_t)ROWS_TOTAL * KG_];      // 41.9 MB  a = x@clusters
__device__ float          g_colsum[KG_];
__device__ float          g_colsumsq[KG_];
__device__ __nv_bfloat16  g_at_hi[(size_t)B_ * K_ * N_];      // 16 MB  assignment^T hi
__device__ __nv_bfloat16  g_at_lo[(size_t)B_ * K_ * N_];      // 16 MB  assignment^T lo
__device__ float          g_asum[B_ * K_];
__device__ float          g_nrm2[B_ * K_];
__device__ float          g_vraw[(size_t)B_ * K_ * D_];       // 8 MB   vlad (B,K,D) pre-norm

// ---------------- helpers ---------------------------------------------------
__device__ __forceinline__ void mma16816(float* c, const uint32_t* a, const uint32_t* b) {
    asm volatile(
        "mma.sync.aligned.m16n8k16.row.col.f32.bf16.bf16.f32 "
        "{%0,%1,%2,%3}, {%4,%5,%6,%7}, {%8,%9}, {%0,%1,%2,%3};\n"
        : "+f"(c[0]), "+f"(c[1]), "+f"(c[2]), "+f"(c[3])
        : "r"(a[0]), "r"(a[1]), "r"(a[2]), "r"(a[3]), "r"(b[0]), "r"(b[1]));
}

__device__ __forceinline__ void split_bf16(float v, __nv_bfloat16& h, __nv_bfloat16& l) {
    h = __float2bfloat16(v);
    l = __float2bfloat16(v - __bfloat162float(h));
}

// ---------------- K0: zero the atomically-accumulated scratch ---------------
__global__ void k0_zero() {
    int t = blockIdx.x * blockDim.x + threadIdx.x;
    if (t < KG_) { g_colsum[t] = 0.0f; g_colsumsq[t] = 0.0f; }
    if (t < B_ * K_) { g_asum[t] = 0.0f; g_nrm2[t] = 0.0f; }
}

// ---------------- K1: a = x @ clusters (131072x512 @ 512x80), bf16x3 --------
// block tile M=128, Ntile=80 (full), K-chunk 32. 256 thr = 4 Mwarps x 2 Nwarps.
// Register-prefetch pipeline: next chunk's global loads issue before MMA work.
// Epilogue fuses per-column sum/sumsq (removes old K2).
#define SA_STRIDE 56
#define SB_STRIDE 40
__global__ __launch_bounds__(256, 2)
void k1_gemm1(const float* __restrict__ x, const float* __restrict__ clusters) {
    __shared__ __nv_bfloat16 sA[2][128 * SA_STRIDE];   // x chunk  [row][k]   hi/lo
    __shared__ __nv_bfloat16 sB[2][KG_ * SB_STRIDE];   // clusters chunk transposed [n][k]
    __shared__ float s_cs[KG_], s_cq[KG_];
    const int tid = threadIdx.x, warp = tid >> 5, lane = tid & 31;
    const int row0 = blockIdx.x * 128;
    const float* xblk = x + (size_t)row0 * D_;

    if (tid < KG_) { s_cs[tid] = 0.0f; s_cq[tid] = 0.0f; }

    const int mrow = (warp & 3) * 32;        // warp's 32 rows
    const int ncol = (warp >> 2) * 40;       // warp's 40 cols (5 x n8)

    float acc[2][5][4];
#pragma unroll
    for (int m = 0; m < 2; m++)
#pragma unroll
        for (int n = 0; n < 5; n++)
#pragma unroll
            for (int j = 0; j < 4; j++) acc[m][n][j] = 0.0f;

    float4 pa[4];
    float  pb[10];
    const int ar = tid >> 3, ac4 = (tid & 7) * 4;

    // ---- prologue: load + store chunk 0
#pragma unroll
    for (int p = 0; p < 4; p++)
        pa[p] = *(const float4*)(xblk + (size_t)(p * 32 + ar) * D_ + ac4);
#pragma unroll
    for (int p = 0; p < 10; p++) {
        int idx = p * 256 + tid;
        pb[p] = clusters[(size_t)(idx / KG_) * KG_ + (idx % KG_)];
    }
    {
#pragma unroll
        for (int p = 0; p < 4; p++) {
            int r = p * 32 + ar;
            float vv[4] = {pa[p].x, pa[p].y, pa[p].z, pa[p].w};
#pragma unroll
            for (int j = 0; j < 4; j++) {
                __nv_bfloat16 h, l; split_bf16(vv[j], h, l);
                sA[0][r * SA_STRIDE + ac4 + j] = h;
                sA[1][r * SA_STRIDE + ac4 + j] = l;
            }
        }
#pragma unroll
        for (int p = 0; p < 10; p++) {
            int idx = p * 256 + tid;
            int kr = idx / KG_, n = idx % KG_;
            __nv_bfloat16 h, l; split_bf16(pb[p], h, l);
            sB[0][n * SB_STRIDE + kr] = h;
            sB[1][n * SB_STRIDE + kr] = l;
        }
    }
    __syncthreads();

    for (int kc32 = 0; kc32 < 16; kc32++) {
        const int kcn = (kc32 + 1) * 32;
        if (kc32 < 15) {   // prefetch next chunk while MMAs run
#pragma unroll
            for (int p = 0; p < 4; p++)
                pa[p] = *(const float4*)(xblk + (size_t)(p * 32 + ar) * D_ + kcn + ac4);
#pragma unroll
            for (int p = 0; p < 10; p++) {
                int idx = p * 256 + tid;
                pb[p] = clusters[(size_t)(kcn + idx / KG_) * KG_ + (idx % KG_)];
            }
        }

#pragma unroll
        for (int ks = 0; ks < 2; ks++) {
            const int kk = ks * 16 + (lane & 3) * 2;
            uint32_t bf[5][2][2];
#pragma unroll
            for (int n = 0; n < 5; n++) {
                int nc = ncol + n * 8 + (lane >> 2);
#pragma unroll
                for (int s = 0; s < 2; s++) {
                    bf[n][s][0] = *(const uint32_t*)(&sB[s][nc * SB_STRIDE + kk]);
                    bf[n][s][1] = *(const uint32_t*)(&sB[s][nc * SB_STRIDE + kk + 8]);
                }
            }
#pragma unroll
            for (int m = 0; m < 2; m++) {
                int r = mrow + m * 16 + (lane >> 2);
                uint32_t ah[4], al[4];
                ah[0] = *(const uint32_t*)(&sA[0][r * SA_STRIDE + kk]);
                ah[1] = *(const uint32_t*)(&sA[0][(r + 8) * SA_STRIDE + kk]);
                ah[2] = *(const uint32_t*)(&sA[0][r * SA_STRIDE + kk + 8]);
                ah[3] = *(const uint32_t*)(&sA[0][(r + 8) * SA_STRIDE + kk + 8]);
                al[0] = *(const uint32_t*)(&sA[1][r * SA_STRIDE + kk]);
                al[1] = *(const uint32_t*)(&sA[1][(r + 8) * SA_STRIDE + kk]);
                al[2] = *(const uint32_t*)(&sA[1][r * SA_STRIDE + kk + 8]);
                al[3] = *(const uint32_t*)(&sA[1][(r + 8) * SA_STRIDE + kk + 8]);
#pragma unroll
                for (int n = 0; n < 5; n++) {
                    mma16816(acc[m][n], ah, bf[n][0]);   // hi*hi
                    mma16816(acc[m][n], ah, bf[n][1]);   // hi*lo
                    mma16816(acc[m][n], al, bf[n][0]);   // lo*hi
                }
            }
        }
        __syncthreads();
        if (kc32 < 15) {
#pragma unroll
            for (int p = 0; p < 4; p++) {
                int r = p * 32 + ar;
                float vv[4] = {pa[p].x, pa[p].y, pa[p].z, pa[p].w};
#pragma unroll
                for (int j = 0; j < 4; j++) {
                    __nv_bfloat16 h, l; split_bf16(vv[j], h, l);
                    sA[0][r * SA_STRIDE + ac4 + j] = h;
                    sA[1][r * SA_STRIDE + ac4 + j] = l;
                }
            }
#pragma unroll
            for (int p = 0; p < 10; p++) {
                int idx = p * 256 + tid;
                int kr = idx / KG_, n = idx % KG_;
                __nv_bfloat16 h, l; split_bf16(pb[p], h, l);
                sB[0][n * SB_STRIDE + kr] = h;
                sB[1][n * SB_STRIDE + kr] = l;
            }
        }
        __syncthreads();
    }

    // epilogue: write a (float2 stores) + fused column stats
#pragma unroll
    for (int m = 0; m < 2; m++)
#pragma unroll
        for (int n = 0; n < 5; n++) {
            int r = row0 + mrow + m * 16 + (lane >> 2);
            int c = ncol + n * 8 + (lane & 3) * 2;
            *(float2*)(&g_a[(size_t)r * KG_ + c])       = make_float2(acc[m][n][0], acc[m][n][1]);
            *(float2*)(&g_a[(size_t)(r + 8) * KG_ + c]) = make_float2(acc[m][n][2], acc[m][n][3]);
        }
    // column stats: per thread, two columns per n (c, c+1); 4 row-values each
#pragma unroll
    for (int n = 0; n < 5; n++) {
#pragma unroll
        for (int j = 0; j < 2; j++) {
            float s = acc[0][n][j] + acc[0][n][j + 2] + acc[1][n][j] + acc[1][n][j + 2];
            float q = acc[0][n][j] * acc[0][n][j] + acc[0][n][j + 2] * acc[0][n][j + 2]
                    + acc[1][n][j] * acc[1][n][j] + acc[1][n][j + 2] * acc[1][n][j + 2];
            // reduce over the 8 row-lanes (lane>>2)
#pragma unroll
            for (int o = 4; o < 32; o <<= 1) {
                s += __shfl_xor_sync(0xffffffffu, s, o);
                q += __shfl_xor_sync(0xffffffffu, q, o);
            }
            if ((lane >> 2) == 0) {
                int c = ncol + n * 8 + (lane & 3) * 2 + j;
                atomicAdd(&s_cs[c], s);
                atomicAdd(&s_cq[c], q);
            }
        }
    }
    __syncthreads();
    if (tid < KG_) {
        atomicAdd(&g_colsum[tid], s_cs[tid]);
        atomicAdd(&g_colsumsq[tid], s_cq[tid]);
    }
}

// ---------------- K3: BN + softmax -> assignment^T (hi/lo) + a_sum ----------
// 64 rows/block, 4 threads per row (20 cols each), quad-shfl reductions.
__global__ __launch_bounds__(256)
void k3_softmax(const float* __restrict__ bn_w, const float* __restrict__ bn_b) {
    __shared__ float srow[64 * 81];
    __shared__ float s_scale[KG_], s_shift[KG_];
    __shared__ float s_part[4][K_];
    const int tid = threadIdx.x;
    const float inv_cnt = 1.0f / (float)ROWS_TOTAL;

    if (tid < KG_) {
        float mean = g_colsum[tid] * inv_cnt;
        float var  = g_colsumsq[tid] * inv_cnt - mean * mean;
        float sc   = rsqrtf(var + 1e-5f) * bn_w[tid];
        s_scale[tid] = sc;
        s_shift[tid] = bn_b[tid] - mean * sc;
    }
    __syncthreads();

    const int row0 = blockIdx.x * 64;
    const float* ab = g_a + (size_t)row0 * KG_;
    for (int i = tid; i < 64 * KG_; i += 256) {
        int r = i / KG_, c = i % KG_;
        srow[r * 81 + c] = ab[i] * s_scale[c] + s_shift[c];
    }
    __syncthreads();

    {
        const int r = tid >> 2, q = tid & 3;
        float* row = srow + r * 81;
        const int j0 = q * 20;
        float mx = row[j0];
#pragma unroll
        for (int j = 1; j < 20; j++) mx = fmaxf(mx, row[j0 + j]);
        mx = fmaxf(mx, __shfl_xor_sync(0xffffffffu, mx, 1));
        mx = fmaxf(mx, __shfl_xor_sync(0xffffffffu, mx, 2));
        float s = 0.0f;
#pragma unroll
        for (int j = 0; j < 20; j++) {
            float e = __expf(row[j0 + j] - mx);
            row[j0 + j] = e; s += e;
        }
        s += __shfl_xor_sync(0xffffffffu, s, 1);
        s += __shfl_xor_sync(0xffffffffu, s, 2);
        float inv = 1.0f / s;
        const int jend = (j0 + 20 < K_) ? 20 : (K_ - j0);   // only first 64 cols matter
#pragma unroll
        for (int j = 0; j < 20; j++)
            if (j < jend) row[j0 + j] *= inv;
    }
    __syncthreads();

    const int b  = row0 >> 11;          // /2048
    const int n0 = row0 & (N_ - 1);
    for (int i = tid; i < K_ * 32; i += 256) {
        int k = i >> 5, rp = (i & 31) * 2;
        float p0 = srow[rp * 81 + k];
        float p1 = srow[(rp + 1) * 81 + k];
        __nv_bfloat16 h0, l0, h1, l1;
        split_bf16(p0, h0, l0);
        split_bf16(p1, h1, l1);
        size_t o = ((size_t)(b * K_ + k)) * N_ + n0 + rp;
        *(__nv_bfloat162*)(g_at_hi + o) = __nv_bfloat162(h0, h1);
        *(__nv_bfloat162*)(g_at_lo + o) = __nv_bfloat162(l0, l1);
    }
    // a_sum partials (64 rows, 4 parts x 16 rows)
    {
        int c = tid & 63, part = tid >> 6;
        float s = 0.0f;
        for (int r = part * 16; r < part * 16 + 16; r++) s += srow[r * 81 + c];
        s_part[part][c] = s;
    }
    __syncthreads();
    if (tid < K_) {
        float s = s_part[0][tid] + s_part[1][tid] + s_part[2][tid] + s_part[3][tid];
        atomicAdd(&g_asum[b * K_ + tid], s);
    }
}

// ---------------- K4: vlad[b,k,d] = sum_n assign^T[k,n]*x[n,d] - asum*c2 ----
// M=64(k) x Ntile=64(d), n-chunk 64, register-prefetch pipeline.
// Epilogue fuses per-(b,k) sumsq (for K5's intra-norm).
#define ST4 72
__global__ __launch_bounds__(256, 2)
void k4_gemm2(const float* __restrict__ x, const float* __restrict__ clusters2) {
    __shared__ __nv_bfloat16 sA[2][K_ * ST4];   // assign^T chunk [k][n]
    __shared__ __nv_bfloat16 sB[2][64 * ST4];   // x chunk transposed [d][n]
    const int tid = threadIdx.x, warp = tid >> 5, lane = tid & 31;
    const int d0 = blockIdx.x * 64;
    const int b  = blockIdx.y;
    const float* xb = x + (size_t)b * N_ * D_;
    const uint2* athi = (const uint2*)(g_at_hi + (size_t)b * K_ * N_);
    const uint2* atlo = (const uint2*)(g_at_lo + (size_t)b * K_ * N_);

    const int mbase = (warp & 1) * 32;
    const int nbase = (warp >> 1) * 16;

    float acc[2][2][4];
#pragma unroll
    for (int m = 0; m < 2; m++)
#pragma unroll
        for (int n = 0; n < 2; n++)
#pragma unroll
            for (int j = 0; j < 4; j++) acc[m][n][j] = 0.0f;

    uint2  ph[4], pl[4];
    float4 px[4];
    const int kA  = tid >> 4;            // partial row index (add p*16)
    const int jA  = tid & 15;            // uint2 index within chunk
    const int dd4 = (tid & 15) * 4;      // 4 d's per thread for x

    // ---- prologue: chunk 0
#pragma unroll
    for (int p = 0; p < 4; p++) {
        int k = p * 16 + kA;
        ph[p] = athi[(size_t)k * (N_ / 4) + jA];
        pl[p] = atlo[(size_t)k * (N_ / 4) + jA];
        int nn = p * 16 + kA;
        px[p] = *(const float4*)(xb + (size_t)nn * D_ + d0 + dd4);
    }
    {
#pragma unroll
        for (int p = 0; p < 4; p++) {
            int k = p * 16 + kA;
            *(uint32_t*)(&sA[0][k * ST4 + jA * 4])     = ph[p].x;
            *(uint32_t*)(&sA[0][k * ST4 + jA * 4 + 2]) = ph[p].y;
            *(uint32_t*)(&sA[1][k * ST4 + jA * 4])     = pl[p].x;
            *(uint32_t*)(&sA[1][k * ST4 + jA * 4 + 2]) = pl[p].y;
            int nn = p * 16 + kA;
            float vv[4] = {px[p].x, px[p].y, px[p].z, px[p].w};
#pragma unroll
            for (int e = 0; e < 4; e++) {
                __nv_bfloat16 h, l; split_bf16(vv[e], h, l);
                sB[0][(dd4 + e) * ST4 + nn] = h;
                sB[1][(dd4 + e) * ST4 + nn] = l;
            }
        }
    }
    __syncthreads();

    for (int it = 0; it < N_ / 64; it++) {
        const int n1 = (it + 1) * 64;
        if (it < N_ / 64 - 1) {   // prefetch next chunk
#pragma unroll
            for (int p = 0; p < 4; p++) {
                int k = p * 16 + kA;
                ph[p] = athi[(size_t)k * (N_ / 4) + n1 / 4 + jA];
                pl[p] = atlo[(size_t)k * (N_ / 4) + n1 / 4 + jA];
                int nn = p * 16 + kA;
                px[p] = *(const float4*)(xb + (size_t)(n1 + nn) * D_ + d0 + dd4);
            }
        }

#pragma unroll
        for (int ks = 0; ks < 4; ks++) {
            const int kk = ks * 16 + (lane & 3) * 2;
            uint32_t bf[2][2][2];
#pragma unroll
            for (int n = 0; n < 2; n++) {
                int dc = nbase + n * 8 + (lane >> 2);
#pragma unroll
                for (int s = 0; s < 2; s++) {
                    bf[n][s][0] = *(const uint32_t*)(&sB[s][dc * ST4 + kk]);
                    bf[n][s][1] = *(const uint32_t*)(&sB[s][dc * ST4 + kk + 8]);
                }
            }
#pragma unroll
            for (int m = 0; m < 2; m++) {
                int r = mbase + m * 16 + (lane >> 2);
                uint32_t ah[4], al[4];
                ah[0] = *(const uint32_t*)(&sA[0][r * ST4 + kk]);
                ah[1] = *(const uint32_t*)(&sA[0][(r + 8) * ST4 + kk]);
                ah[2] = *(const uint32_t*)(&sA[0][r * ST4 + kk + 8]);
                ah[3] = *(const uint32_t*)(&sA[0][(r + 8) * ST4 + kk + 8]);
                al[0] = *(const uint32_t*)(&sA[1][r * ST4 + kk]);
                al[1] = *(const uint32_t*)(&sA[1][(r + 8) * ST4 + kk]);
                al[2] = *(const uint32_t*)(&sA[1][r * ST4 + kk + 8]);
                al[3] = *(const uint32_t*)(&sA[1][(r + 8) * ST4 + kk + 8]);
#pragma unroll
                for (int n = 0; n < 2; n++) {
                    mma16816(acc[m][n], ah, bf[n][0]);
                    mma16816(acc[m][n], ah, bf[n][1]);
                    mma16816(acc[m][n], al, bf[n][0]);
                }
            }
        }
        __syncthreads();
        if (it < N_ / 64 - 1) {
#pragma unroll
            for (int p = 0; p < 4; p++) {
                int k = p * 16 + kA;
                *(uint32_t*)(&sA[0][k * ST4 + jA * 4])     = ph[p].x;
                *(uint32_t*)(&sA[0][k * ST4 + jA * 4 + 2]) = ph[p].y;
                *(uint32_t*)(&sA[1][k * ST4 + jA * 4])     = pl[p].x;
                *(uint32_t*)(&sA[1][k * ST4 + jA * 4 + 2]) = pl[p].y;
                int nn = p * 16 + kA;
                float vv[4] = {px[p].x, px[p].y, px[p].z, px[p].w};
#pragma unroll
                for (int e = 0; e < 4; e++) {
                    __nv_bfloat16 h, l; split_bf16(vv[e], h, l);
                    sB[0][(dd4 + e) * ST4 + nn] = h;
                    sB[1][(dd4 + e) * ST4 + nn] = l;
                }
            }
        }
        __syncthreads();
    }

    // epilogue: subtract a_sum*clusters2, write vraw, accumulate sumsq per (b,k)
    float sq[2][2] = {{0.0f, 0.0f}, {0.0f, 0.0f}};
#pragma unroll
    for (int m = 0; m < 2; m++)
#pragma unroll
        for (int n = 0; n < 2; n++) {
            int kbase = mbase + m * 16 + (lane >> 2);
            int d = d0 + nbase + n * 8 + (lane & 3) * 2;
#pragma unroll
            for (int h = 0; h < 2; h++) {
                int kk = kbase + h * 8;
                float as = g_asum[b * K_ + kk];
                float v0 = acc[m][n][h * 2 + 0] - as * clusters2[(size_t)(d + 0) * K_ + kk];
                float v1 = acc[m][n][h * 2 + 1] - as * clusters2[(size_t)(d + 1) * K_ + kk];
                *(float2*)(&g_vraw[((size_t)(b * K_ + kk)) * D_ + d]) = make_float2(v0, v1);
                sq[m][h] += v0 * v0 + v1 * v1;
            }
        }
#pragma unroll
    for (int m = 0; m < 2; m++)
#pragma unroll
        for (int h = 0; h < 2; h++) {
            float s = sq[m][h];
            s += __shfl_xor_sync(0xffffffffu, s, 1);
            s += __shfl_xor_sync(0xffffffffu, s, 2);
            if ((lane & 3) == 0) {
                int kk = mbase + m * 16 + (lane >> 2) + h * 8;
                atomicAdd(&g_nrm2[b * K_ + kk], s);
            }
        }
}

// ---------------- K5: scale by intra + global norms, transpose --------------
__global__ __launch_bounds__(256)
void k5_norm(float* __restrict__ out) {
    __shared__ float tile[K_ * 129];
    __shared__ float s_scale[K_];
    __shared__ float s_red[K_];
    __shared__ float s_g;
    const int tid = threadIdx.x, lane = tid & 31;
    const int b  = blockIdx.y;
    const int dc = blockIdx.x * 128;
    const float* vb = g_vraw + (size_t)b * K_ * D_;

    if (tid < K_) {
        float n2 = g_nrm2[b * K_ + tid];
        float n  = sqrtf(n2);
        float sc = 1.0f / fmaxf(n, 1e-12f);
        s_scale[tid] = sc;
        float vn = n * sc;
        s_red[tid] = vn * vn;
    }
    __syncthreads();
    if (tid < 32) {
        float s = s_red[lane] + s_red[lane + 32];
#pragma unroll
        for (int o = 16; o; o >>= 1) s += __shfl_xor_sync(0xffffffffu, s, o);
        if (lane == 0) s_g = 1.0f / fmaxf(sqrtf(s), 1e-12f);
    }
    __syncthreads();
    const float g = s_g;

    for (int i = tid; i < K_ * 128; i += 256) {
        int k = i >> 7, d = i & 127;
        tile[k * 129 + d] = vb[(size_t)k * D_ + dc + d] * s_scale[k] * g;
    }
    __syncthreads();
    float* ob = out + (size_t)b * (D_ * K_);
    for (int i = tid; i < K_ * 128; i += 256) {
        int d = i >> 6, k = i & 63;
        ob[(size_t)(dc + d) * K_ + k] = tile[k * 129 + d];
    }
}

// ---------------- launch ----------------------------------------------------
extern "C" void kernel_launch(void* const* d_in, const int* in_sizes, int n_in,
                              void* d_out, int out_size) {
    const float* x         = (const float*)d_in[0];   // (64, 2048, 512)
    const float* clusters  = (const float*)d_in[1];   // (512, 80)
    const float* clusters2 = (const float*)d_in[2];   // (1, 512, 64)
    const float* bn_w      = (const float*)d_in[3];   // (80,)
    const float* bn_b      = (const float*)d_in[4];   // (80,)
    float* out = (float*)d_out;                       // (64, 32768)

    k0_zero<<<16, 256>>>();
    k1_gemm1<<<ROWS_TOTAL / 128, 256>>>(x, clusters);
    k3_softmax<<<ROWS_TOTAL / 64, 256>>>(bn_w, bn_b);
    k4_gemm2<<<dim3(D_ / 64, B_), 256>>>(x, clusters2);
    k5_norm<<<dim3(D_ / 128, B_), 256>>>(out);
}

// round 4
// speedup vs baseline: 1.9075x; 1.9075x over previous
#include <cuda_runtime.h>
#include <cuda_bf16.h>
#include <stdint.h>

// Problem constants (fixed by the reference)
#define B_   64
#define N_   2048
#define D_   512
#define K_   64
#define KG_  80
#define ROWS_TOTAL (B_ * N_)         // 131072

// ---------------- scratch (__device__ globals: allocation-free) -------------
__device__ float          g_a[(size_t)ROWS_TOTAL * KG_];      // 41.9 MB
__device__ float          g_colsum[KG_];
__device__ float          g_colsumsq[KG_];
__device__ __nv_bfloat16  g_ch[KG_ * D_];                     // clusters^T hi [n][d]
__device__ __nv_bfloat16  g_cl[KG_ * D_];                     // clusters^T lo [n][d]
__device__ __nv_bfloat16  g_at_hi[(size_t)B_ * K_ * N_];      // 16 MB assignment^T hi
__device__ __nv_bfloat16  g_at_lo[(size_t)B_ * K_ * N_];      // 16 MB assignment^T lo
__device__ float          g_asum[B_ * K_];
__device__ float          g_nrm2[B_ * K_];
__device__ float          g_vraw[(size_t)B_ * K_ * D_];       // 8 MB vlad (B,K,D)

// ---------------- helpers ---------------------------------------------------
__device__ __forceinline__ void mma16816(float* c, const uint32_t* a, const uint32_t* b) {
    asm volatile(
        "mma.sync.aligned.m16n8k16.row.col.f32.bf16.bf16.f32 "
        "{%0,%1,%2,%3}, {%4,%5,%6,%7}, {%8,%9}, {%0,%1,%2,%3};\n"
        : "+f"(c[0]), "+f"(c[1]), "+f"(c[2]), "+f"(c[3])
        : "r"(a[0]), "r"(a[1]), "r"(a[2]), "r"(a[3]), "r"(b[0]), "r"(b[1]));
}
__device__ __forceinline__ void split_bf16(float v, __nv_bfloat16& h, __nv_bfloat16& l) {
    h = __float2bfloat16(v);
    l = __float2bfloat16(v - __bfloat162float(h));
}
__device__ __forceinline__ uint32_t pack_bf2(__nv_bfloat16 a, __nv_bfloat16 b) {
    __nv_bfloat162 t(a, b);
    return *(uint32_t*)&t;
}
__device__ __forceinline__ void ldsm4(uint32_t* r, uint32_t addr) {
    asm volatile("ldmatrix.sync.aligned.m8n8.x4.shared.b16 {%0,%1,%2,%3}, [%4];"
        : "=r"(r[0]), "=r"(r[1]), "=r"(r[2]), "=r"(r[3]) : "r"(addr));
}
__device__ __forceinline__ void ldsm4t(uint32_t* r, uint32_t addr) {
    asm volatile("ldmatrix.sync.aligned.m8n8.x4.trans.shared.b16 {%0,%1,%2,%3}, [%4];"
        : "=r"(r[0]), "=r"(r[1]), "=r"(r[2]), "=r"(r[3]) : "r"(addr));
}
__device__ __forceinline__ void ldsm2(uint32_t* r, uint32_t addr) {
    asm volatile("ldmatrix.sync.aligned.m8n8.x2.shared.b16 {%0,%1}, [%2];"
        : "=r"(r[0]), "=r"(r[1]) : "r"(addr));
}
__device__ __forceinline__ void cp16(uint32_t dst, const void* src) {
    asm volatile("cp.async.cg.shared.global [%0], [%1], 16;" :: "r"(dst), "l"(src));
}
__device__ __forceinline__ void cp_commit() { asm volatile("cp.async.commit_group;"); }
__device__ __forceinline__ void cp_wait0()  { asm volatile("cp.async.wait_group 0;" ::: "memory"); }

// ---------------- K0: zero accumulators + pre-split clusters^T ---------------
__global__ void k0_init(const float* __restrict__ clusters) {
    int t = blockIdx.x * 256 + threadIdx.x;
    if (t < KG_) { g_colsum[t] = 0.0f; g_colsumsq[t] = 0.0f; }
    if (t < B_ * K_) { g_asum[t] = 0.0f; g_nrm2[t] = 0.0f; }
    if (t < D_ * KG_) {
        int d = t / KG_, n = t % KG_;
        __nv_bfloat16 h, l; split_bf16(clusters[t], h, l);
        g_ch[n * D_ + d] = h;
        g_cl[n * D_ + d] = l;
    }
}

// ---------------- K1: a = x @ clusters, bf16x3, ldmatrix + double buffer ----
// Block: 128 rows x 80 cols, kchunk 32, 8 warps = 4m x 2n (warp 32 x 40).
#define S1A 40
#define S1B 40
#define BUF1 16640   // halves per buffer: 2*128*40 + 2*80*40
__global__ __launch_bounds__(256, 2)
void k1_gemm1(const float* __restrict__ x) {
    extern __shared__ __align__(16) __nv_bfloat16 ds[];
    __shared__ float s_cs[KG_], s_cq[KG_];
    const int tid = threadIdx.x, warp = tid >> 5, lane = tid & 31;
    const int row0 = blockIdx.x * 128;
    const float* xblk = x + (size_t)row0 * D_;
    const uint32_t sbase = (uint32_t)__cvta_generic_to_shared(ds);
    if (tid < KG_) { s_cs[tid] = 0.0f; s_cq[tid] = 0.0f; }

    const int mrow = (warp & 3) * 32, ncol = (warp >> 2) * 40;

    float acc[2][5][4];
#pragma unroll
    for (int m = 0; m < 2; m++)
#pragma unroll
        for (int t = 0; t < 5; t++)
#pragma unroll
            for (int j = 0; j < 4; j++) acc[m][t][j] = 0.0f;

    float4 pa[4];
    const int ar = tid >> 3, ac4 = (tid & 7) * 4;

    // ---- prologue: chunk 0
#pragma unroll
    for (int p = 0; p < 3; p++) {
        int idx = tid + p * 256;
        if (idx < 640) {
            int s = idx >= 320 ? 1 : 0;
            int r = (idx - s * 320) >> 2, seg = idx & 3;
            const __nv_bfloat16* src = (s ? g_cl : g_ch) + r * D_ + seg * 8;
            cp16(sbase + (uint32_t)((BUF1 * 0 + 10240 + s * 3200) + r * S1B + seg * 8) * 2, src);
        }
    }
    cp_commit();
#pragma unroll
    for (int p = 0; p < 4; p++)
        pa[p] = *(const float4*)(xblk + (size_t)(p * 32 + ar) * D_ + ac4);
#pragma unroll
    for (int p = 0; p < 4; p++) {
        int r = p * 32 + ar;
        float vv[4] = {pa[p].x, pa[p].y, pa[p].z, pa[p].w};
        __nv_bfloat16 h[4], l[4];
#pragma unroll
        for (int j = 0; j < 4; j++) split_bf16(vv[j], h[j], l[j]);
        *(uint2*)(&ds[0 * 5120 + r * S1A + ac4]) = make_uint2(pack_bf2(h[0], h[1]), pack_bf2(h[2], h[3]));
        *(uint2*)(&ds[1 * 5120 + r * S1A + ac4]) = make_uint2(pack_bf2(l[0], l[1]), pack_bf2(l[2], l[3]));
    }
    cp_wait0();
    __syncthreads();

    for (int c = 0; c < 16; c++) {
        const int buf = c & 1, nb = buf ^ 1, kcn = (c + 1) * 32;
        const int sa0 = buf * BUF1, sb0 = buf * BUF1 + 10240;
        if (c < 15) {
#pragma unroll
            for (int p = 0; p < 3; p++) {
                int idx = tid + p * 256;
                if (idx < 640) {
                    int s = idx >= 320 ? 1 : 0;
                    int r = (idx - s * 320) >> 2, seg = idx & 3;
                    const __nv_bfloat16* src = (s ? g_cl : g_ch) + r * D_ + kcn + seg * 8;
                    cp16(sbase + (uint32_t)((nb * BUF1 + 10240 + s * 3200) + r * S1B + seg * 8) * 2, src);
                }
            }
            cp_commit();
#pragma unroll
            for (int p = 0; p < 4; p++)
                pa[p] = *(const float4*)(xblk + (size_t)(p * 32 + ar) * D_ + kcn + ac4);
        }

#pragma unroll
        for (int ks = 0; ks < 2; ks++) {
            const int kk0 = ks * 16;
            uint32_t AH[2][4], AL[2][4];
#pragma unroll
            for (int m = 0; m < 2; m++) {
                int rr = mrow + m * 16 + (lane & 7) + ((lane >> 3) & 1) * 8;
                int cc = kk0 + ((lane >> 4) & 1) * 8;
                ldsm4(AH[m], sbase + (uint32_t)(sa0 + 0 * 5120 + rr * S1A + cc) * 2);
                ldsm4(AL[m], sbase + (uint32_t)(sa0 + 1 * 5120 + rr * S1A + cc) * 2);
            }
            uint32_t BH[5][2], BL[5][2];
#pragma unroll
            for (int tp = 0; tp < 2; tp++) {
                int nn = ncol + tp * 16 + (lane & 7) + ((lane >> 4) & 1) * 8;
                int cc = kk0 + ((lane >> 3) & 1) * 8;
                uint32_t r4[4];
                ldsm4(r4, sbase + (uint32_t)(sb0 + 0 * 3200 + nn * S1B + cc) * 2);
                BH[2 * tp][0] = r4[0]; BH[2 * tp][1] = r4[1];
                BH[2 * tp + 1][0] = r4[2]; BH[2 * tp + 1][1] = r4[3];
                ldsm4(r4, sbase + (uint32_t)(sb0 + 1 * 3200 + nn * S1B + cc) * 2);
                BL[2 * tp][0] = r4[0]; BL[2 * tp][1] = r4[1];
                BL[2 * tp + 1][0] = r4[2]; BL[2 * tp + 1][1] = r4[3];
            }
            {
                int nn = ncol + 32 + (lane & 7);
                int cc = kk0 + ((lane >> 3) & 1) * 8;
                ldsm2(BH[4], sbase + (uint32_t)(sb0 + 0 * 3200 + nn * S1B + cc) * 2);
                ldsm2(BL[4], sbase + (uint32_t)(sb0 + 1 * 3200 + nn * S1B + cc) * 2);
            }
#pragma unroll
            for (int m = 0; m < 2; m++)
#pragma unroll
                for (int t = 0; t < 5; t++) {
                    mma16816(acc[m][t], AH[m], BH[t]);   // hi*hi
                    mma16816(acc[m][t], AH[m], BL[t]);   // hi*lo
                    mma16816(acc[m][t], AL[m], BH[t]);   // lo*hi
                }
        }

        if (c < 15) {
#pragma unroll
            for (int p = 0; p < 4; p++) {
                int r = p * 32 + ar;
                float vv[4] = {pa[p].x, pa[p].y, pa[p].z, pa[p].w};
                __nv_bfloat16 h[4], l[4];
#pragma unroll
                for (int j = 0; j < 4; j++) split_bf16(vv[j], h[j], l[j]);
                *(uint2*)(&ds[nb * BUF1 + 0 * 5120 + r * S1A + ac4]) = make_uint2(pack_bf2(h[0], h[1]), pack_bf2(h[2], h[3]));
                *(uint2*)(&ds[nb * BUF1 + 1 * 5120 + r * S1A + ac4]) = make_uint2(pack_bf2(l[0], l[1]), pack_bf2(l[2], l[3]));
            }
            cp_wait0();
        }
        __syncthreads();
    }

    // epilogue: write a + fused column stats
#pragma unroll
    for (int m = 0; m < 2; m++)
#pragma unroll
        for (int t = 0; t < 5; t++) {
            int r = row0 + mrow + m * 16 + (lane >> 2);
            int col = ncol + t * 8 + (lane & 3) * 2;
            *(float2*)(&g_a[(size_t)r * KG_ + col])       = make_float2(acc[m][t][0], acc[m][t][1]);
            *(float2*)(&g_a[(size_t)(r + 8) * KG_ + col]) = make_float2(acc[m][t][2], acc[m][t][3]);
        }
#pragma unroll
    for (int t = 0; t < 5; t++)
#pragma unroll
        for (int j = 0; j < 2; j++) {
            float s = acc[0][t][j] + acc[0][t][j + 2] + acc[1][t][j] + acc[1][t][j + 2];
            float q = acc[0][t][j] * acc[0][t][j] + acc[0][t][j + 2] * acc[0][t][j + 2]
                    + acc[1][t][j] * acc[1][t][j] + acc[1][t][j + 2] * acc[1][t][j + 2];
#pragma unroll
            for (int o = 4; o < 32; o <<= 1) {
                s += __shfl_xor_sync(0xffffffffu, s, o);
                q += __shfl_xor_sync(0xffffffffu, q, o);
            }
            if ((lane >> 2) == 0) {
                int col = ncol + t * 8 + (lane & 3) * 2 + j;
                atomicAdd(&s_cs[col], s);
                atomicAdd(&s_cq[col], q);
            }
        }
    __syncthreads();
    if (tid < KG_) {
        atomicAdd(&g_colsum[tid], s_cs[tid]);
        atomicAdd(&g_colsumsq[tid], s_cq[tid]);
    }
}

// ---------------- K3: BN + softmax -> assignment^T (hi/lo) + a_sum ----------
__global__ __launch_bounds__(256)
void k3_softmax(const float* __restrict__ bn_w, const float* __restrict__ bn_b) {
    __shared__ float srow[64 * 81];
    __shared__ float s_scale[KG_], s_shift[KG_];
    __shared__ float s_part[4][K_];
    const int tid = threadIdx.x;
    const float inv_cnt = 1.0f / (float)ROWS_TOTAL;

    if (tid < KG_) {
        float mean = g_colsum[tid] * inv_cnt;
        float var  = g_colsumsq[tid] * inv_cnt - mean * mean;
        float sc   = rsqrtf(var + 1e-5f) * bn_w[tid];
        s_scale[tid] = sc;
        s_shift[tid] = bn_b[tid] - mean * sc;
    }
    __syncthreads();

    const int row0 = blockIdx.x * 64;
    const float* ab = g_a + (size_t)row0 * KG_;
    for (int i = tid; i < 64 * KG_; i += 256) {
        int r = i / KG_, col = i % KG_;
        srow[r * 81 + col] = ab[i] * s_scale[col] + s_shift[col];
    }
    __syncthreads();

    {
        const int r = tid >> 2, q = tid & 3;
        float* row = srow + r * 81;
        const int j0 = q * 20;
        float mx = row[j0];
#pragma unroll
        for (int j = 1; j < 20; j++) mx = fmaxf(mx, row[j0 + j]);
        mx = fmaxf(mx, __shfl_xor_sync(0xffffffffu, mx, 1));
        mx = fmaxf(mx, __shfl_xor_sync(0xffffffffu, mx, 2));
        float s = 0.0f;
#pragma unroll
        for (int j = 0; j < 20; j++) {
            float e = __expf(row[j0 + j] - mx);
            row[j0 + j] = e; s += e;
        }
        s += __shfl_xor_sync(0xffffffffu, s, 1);
        s += __shfl_xor_sync(0xffffffffu, s, 2);
        float inv = 1.0f / s;
        const int jend = (j0 + 20 < K_) ? 20 : (K_ - j0);
#pragma unroll
        for (int j = 0; j < 20; j++)
            if (j < jend) row[j0 + j] *= inv;
    }
    __syncthreads();

    const int b  = row0 >> 11;
    const int n0 = row0 & (N_ - 1);
    for (int i = tid; i < K_ * 32; i += 256) {
        int k = i >> 5, rp = (i & 31) * 2;
        float p0 = srow[rp * 81 + k];
        float p1 = srow[(rp + 1) * 81 + k];
        __nv_bfloat16 h0, l0, h1, l1;
        split_bf16(p0, h0, l0);
        split_bf16(p1, h1, l1);
        size_t o = ((size_t)(b * K_ + k)) * N_ + n0 + rp;
        *(__nv_bfloat162*)(g_at_hi + o) = __nv_bfloat162(h0, h1);
        *(__nv_bfloat162*)(g_at_lo + o) = __nv_bfloat162(l0, l1);
    }
    {
        int col = tid & 63, part = tid >> 6;
        float s = 0.0f;
        for (int r = part * 16; r < part * 16 + 16; r++) s += srow[r * 81 + col];
        s_part[part][col] = s;
    }
    __syncthreads();
    if (tid < K_) {
        float s = s_part[0][tid] + s_part[1][tid] + s_part[2][tid] + s_part[3][tid];
        atomicAdd(&g_asum[b * K_ + tid], s);
    }
}

// ---------------- K4: vlad = assign^T @ x - asum*c2, ldmatrix + cp.async ----
// Block 64k x 128d, nchunk 64, double buffer. 8 warps = 2m x 4d (warp 32x32).
#define S4A 72
#define S4X 136
#define BUF4 26624   // halves: 2*64*72 + 2*64*136
__global__ __launch_bounds__(256, 2)
void k4_gemm2(const float* __restrict__ x, const float* __restrict__ c2) {
    extern __shared__ __align__(16) __nv_bfloat16 ds[];
    const int tid = threadIdx.x, warp = tid >> 5, lane = tid & 31;
    const int d0 = blockIdx.x * 128;
    const int b  = blockIdx.y;
    const float* xb = x + (size_t)b * N_ * D_;
    const __nv_bfloat16* athi = g_at_hi + (size_t)b * K_ * N_;
    const __nv_bfloat16* atlo = g_at_lo + (size_t)b * K_ * N_;
    const uint32_t sbase = (uint32_t)__cvta_generic_to_shared(ds);

    const int mbase = (warp & 1) * 32, dwb = (warp >> 1) * 32;

    float acc[2][4][4];
#pragma unroll
    for (int m = 0; m < 2; m++)
#pragma unroll
        for (int t = 0; t < 4; t++)
#pragma unroll
            for (int j = 0; j < 4; j++) acc[m][t][j] = 0.0f;

    float4 px[8];

    // ---- prologue: chunk 0
#pragma unroll
    for (int p = 0; p < 4; p++) {
        int idx = tid + p * 256;
        int s = idx >> 9, rem = idx & 511;
        int r = rem >> 3, seg = rem & 7;
        const __nv_bfloat16* src = (s ? atlo : athi) + (size_t)r * N_ + seg * 8;
        cp16(sbase + (uint32_t)((s * 4608) + r * S4A + seg * 8) * 2, src);
    }
    cp_commit();
#pragma unroll
    for (int p = 0; p < 8; p++) {
        int idx = tid + p * 256;
        int n = idx >> 5, d4 = (idx & 31) * 4;
        px[p] = *(const float4*)(xb + (size_t)n * D_ + d0 + d4);
    }
#pragma unroll
    for (int p = 0; p < 8; p++) {
        int idx = tid + p * 256;
        int n = idx >> 5, d4 = (idx & 31) * 4;
        float vv[4] = {px[p].x, px[p].y, px[p].z, px[p].w};
        __nv_bfloat16 h[4], l[4];
#pragma unroll
        for (int j = 0; j < 4; j++) split_bf16(vv[j], h[j], l[j]);
        *(uint2*)(&ds[9216 + 0 * 8704 + n * S4X + d4]) = make_uint2(pack_bf2(h[0], h[1]), pack_bf2(h[2], h[3]));
        *(uint2*)(&ds[9216 + 1 * 8704 + n * S4X + d4]) = make_uint2(pack_bf2(l[0], l[1]), pack_bf2(l[2], l[3]));
    }
    cp_wait0();
    __syncthreads();

    for (int it = 0; it < 32; it++) {
        const int buf = it & 1, nb = buf ^ 1, n1 = (it + 1) * 64;
        const int sa0 = buf * BUF4, sx0 = buf * BUF4 + 9216;
        if (it < 31) {
#pragma unroll
            for (int p = 0; p < 4; p++) {
                int idx = tid + p * 256;
                int s = idx >> 9, rem = idx & 511;
                int r = rem >> 3, seg = rem & 7;
                const __nv_bfloat16* src = (s ? atlo : athi) + (size_t)r * N_ + n1 + seg * 8;
                cp16(sbase + (uint32_t)((nb * BUF4 + s * 4608) + r * S4A + seg * 8) * 2, src);
            }
            cp_commit();
#pragma unroll
            for (int p = 0; p < 8; p++) {
                int idx = tid + p * 256;
                int n = idx >> 5, d4 = (idx & 31) * 4;
                px[p] = *(const float4*)(xb + (size_t)(n1 + n) * D_ + d0 + d4);
            }
        }

#pragma unroll
        for (int ks = 0; ks < 4; ks++) {
            const int kk0 = ks * 16;
            uint32_t AH[2][4], AL[2][4];
#pragma unroll
            for (int m = 0; m < 2; m++) {
                int rr = mbase + m * 16 + (lane & 7) + ((lane >> 3) & 1) * 8;
                int cc = kk0 + ((lane >> 4) & 1) * 8;
                ldsm4(AH[m], sbase + (uint32_t)(sa0 + 0 * 4608 + rr * S4A + cc) * 2);
                ldsm4(AL[m], sbase + (uint32_t)(sa0 + 1 * 4608 + rr * S4A + cc) * 2);
            }
            uint32_t BH[4][2], BL[4][2];
#pragma unroll
            for (int dp = 0; dp < 2; dp++) {
                int rr = kk0 + (lane & 7) + ((lane >> 3) & 1) * 8;
                int cc = dwb + dp * 16 + ((lane >> 4) & 1) * 8;
                uint32_t r4[4];
                ldsm4t(r4, sbase + (uint32_t)(sx0 + 0 * 8704 + rr * S4X + cc) * 2);
                BH[2 * dp][0] = r4[0]; BH[2 * dp][1] = r4[1];
                BH[2 * dp + 1][0] = r4[2]; BH[2 * dp + 1][1] = r4[3];
                ldsm4t(r4, sbase + (uint32_t)(sx0 + 1 * 8704 + rr * S4X + cc) * 2);
                BL[2 * dp][0] = r4[0]; BL[2 * dp][1] = r4[1];
                BL[2 * dp + 1][0] = r4[2]; BL[2 * dp + 1][1] = r4[3];
            }
#pragma unroll
            for (int m = 0; m < 2; m++)
#pragma unroll
                for (int t = 0; t < 4; t++) {
                    mma16816(acc[m][t], AH[m], BH[t]);   // a_hi * x_hi
                    mma16816(acc[m][t], AL[m], BH[t]);   // a_lo * x_hi
                    mma16816(acc[m][t], AH[m], BL[t]);   // a_hi * x_lo
                }
        }

        if (it < 31) {
#pragma unroll
            for (int p = 0; p < 8; p++) {
                int idx = tid + p * 256;
                int n = idx >> 5, d4 = (idx & 31) * 4;
                float vv[4] = {px[p].x, px[p].y, px[p].z, px[p].w};
                __nv_bfloat16 h[4], l[4];
#pragma unroll
                for (int j = 0; j < 4; j++) split_bf16(vv[j], h[j], l[j]);
                *(uint2*)(&ds[nb * BUF4 + 9216 + 0 * 8704 + n * S4X + d4]) = make_uint2(pack_bf2(h[0], h[1]), pack_bf2(h[2], h[3]));
                *(uint2*)(&ds[nb * BUF4 + 9216 + 1 * 8704 + n * S4X + d4]) = make_uint2(pack_bf2(l[0], l[1]), pack_bf2(l[2], l[3]));
            }
            cp_wait0();
        }
        __syncthreads();
    }

    // epilogue: subtract a_sum*clusters2, write vraw, fused sumsq per (b,k)
    float sq[2][2] = {{0.0f, 0.0f}, {0.0f, 0.0f}};
#pragma unroll
    for (int m = 0; m < 2; m++)
#pragma unroll
        for (int t = 0; t < 4; t++) {
            int kbase = mbase + m * 16 + (lane >> 2);
            int d = d0 + dwb + t * 8 + (lane & 3) * 2;
#pragma unroll
            for (int h = 0; h < 2; h++) {
                int kk = kbase + h * 8;
                float as = g_asum[b * K_ + kk];
                float v0 = acc[m][t][h * 2 + 0] - as * c2[(size_t)(d + 0) * K_ + kk];
                float v1 = acc[m][t][h * 2 + 1] - as * c2[(size_t)(d + 1) * K_ + kk];
                *(float2*)(&g_vraw[((size_t)(b * K_ + kk)) * D_ + d]) = make_float2(v0, v1);
                sq[m][h] += v0 * v0 + v1 * v1;
            }
        }
#pragma unroll
    for (int m = 0; m < 2; m++)
#pragma unroll
        for (int h = 0; h < 2; h++) {
            float s = sq[m][h];
            s += __shfl_xor_sync(0xffffffffu, s, 1);
            s += __shfl_xor_sync(0xffffffffu, s, 2);
            if ((lane & 3) == 0) {
                int kk = mbase + m * 16 + (lane >> 2) + h * 8;
                atomicAdd(&g_nrm2[b * K_ + kk], s);
            }
        }
}

// ---------------- K5: scale by intra + global norms, transpose --------------
__global__ __launch_bounds__(256)
void k5_norm(float* __restrict__ out) {
    __shared__ float tile[K_ * 129];
    __shared__ float s_scale[K_];
    __shared__ float s_red[K_];
    __shared__ float s_g;
    const int tid = threadIdx.x, lane = tid & 31;
    const int b  = blockIdx.y;
    const int dc = blockIdx.x * 128;
    const float* vb = g_vraw + (size_t)b * K_ * D_;

    if (tid < K_) {
        float n2 = g_nrm2[b * K_ + tid];
        float n  = sqrtf(n2);
        float sc = 1.0f / fmaxf(n, 1e-12f);
        s_scale[tid] = sc;
        float vn = n * sc;
        s_red[tid] = vn * vn;
    }
    __syncthreads();
    if (tid < 32) {
        float s = s_red[lane] + s_red[lane + 32];
#pragma unroll
        for (int o = 16; o; o >>= 1) s += __shfl_xor_sync(0xffffffffu, s, o);
        if (lane == 0) s_g = 1.0f / fmaxf(sqrtf(s), 1e-12f);
    }
    __syncthreads();
    const float g = s_g;

    for (int i = tid; i < K_ * 128; i += 256) {
        int k = i >> 7, d = i & 127;
        tile[k * 129 + d] = vb[(size_t)k * D_ + dc + d] * s_scale[k] * g;
    }
    __syncthreads();
    float* ob = out + (size_t)b * (D_ * K_);
    for (int i = tid; i < K_ * 128; i += 256) {
        int d = i >> 6, k = i & 63;
        ob[(size_t)(dc + d) * K_ + k] = tile[k * 129 + d];
    }
}

// ---------------- launch ----------------------------------------------------
extern "C" void kernel_launch(void* const* d_in, const int* in_sizes, int n_in,
                              void* d_out, int out_size) {
    const float* x         = (const float*)d_in[0];   // (64, 2048, 512)
    const float* clusters  = (const float*)d_in[1];   // (512, 80)
    const float* clusters2 = (const float*)d_in[2];   // (1, 512, 64)
    const float* bn_w      = (const float*)d_in[3];   // (80,)
    const float* bn_b      = (const float*)d_in[4];   // (80,)
    float* out = (float*)d_out;                       // (64, 32768)

    cudaFuncSetAttribute(k1_gemm1, cudaFuncAttributeMaxDynamicSharedMemorySize, 2 * BUF1 * 2);
    cudaFuncSetAttribute(k4_gemm2, cudaFuncAttributeMaxDynamicSharedMemorySize, 2 * BUF4 * 2);

    k0_init<<<160, 256>>>(clusters);
    k1_gemm1<<<ROWS_TOTAL / 128, 256, 2 * BUF1 * 2>>>(x);
    k3_softmax<<<ROWS_TOTAL / 64, 256>>>(bn_w, bn_b);
    k4_gemm2<<<dim3(D_ / 128, B_), 256, 2 * BUF4 * 2>>>(x, clusters2);
    k5_norm<<<dim3(D_ / 128, B_), 256>>>(out);
}